// round 6
// baseline (speedup 1.0000x reference)
#include <cuda_runtime.h>
#include <cuda_bf16.h>
#include <math.h>
#include <stdint.h>

#define ROWS   4096
#define DMODEL 1024
#define TSEQ   2048
#define DK     64
#define NGRP   32
#define OUT_ELEMS 4194304
#define ATTN_PER_G 4194304
#define GRP_STRIDE 131072

// Scratch
__device__ float g_q[ROWS * DMODEL];
__device__ float g_k[ROWS * DMODEL];
__device__ float g_v[ROWS * DMODEL];
__device__ __nv_bfloat16 g_xh[ROWS * DMODEL], g_xl[ROWS * DMODEL];   // packed frags
__device__ __nv_bfloat16 g_qh[ROWS * DMODEL], g_ql[ROWS * DMODEL];   // packed per-group
__device__ __nv_bfloat16 g_kh[ROWS * DMODEL], g_kl[ROWS * DMODEL];   // group-slab row-major
__device__ __nv_bfloat16 g_wh[3 * DMODEL * DMODEL], g_wl[3 * DMODEL * DMODEL];
__device__ __nv_bfloat16 g_vh[NGRP * DK * TSEQ], g_vl[NGRP * DK * TSEQ];

// ===========================================================================
__device__ __forceinline__ uint32_t smem_u32(const void* p) {
    uint32_t a;
    asm("{ .reg .u64 t; cvta.to.shared.u64 t, %1; cvt.u32.u64 %0, t; }"
        : "=r"(a) : "l"(p));
    return a;
}

__device__ __forceinline__ void ldsm4(uint32_t* r, uint32_t addr) {
    asm volatile("ldmatrix.sync.aligned.m8n8.x4.shared.b16 {%0,%1,%2,%3}, [%4];"
                 : "=r"(r[0]), "=r"(r[1]), "=r"(r[2]), "=r"(r[3]) : "r"(addr));
}

__device__ __forceinline__ void mma16816(float* c, const uint32_t* a,
                                         const uint32_t* b) {
    asm volatile(
        "mma.sync.aligned.m16n8k16.row.col.f32.bf16.bf16.f32 "
        "{%0,%1,%2,%3}, {%4,%5,%6,%7}, {%8,%9}, {%0,%1,%2,%3};"
        : "+f"(c[0]), "+f"(c[1]), "+f"(c[2]), "+f"(c[3])
        : "r"(a[0]), "r"(a[1]), "r"(a[2]), "r"(a[3]), "r"(b[0]), "r"(b[1]));
}

__device__ __forceinline__ void split_f4(float4 v, uint2& hi, uint2& lo) {
    uint32_t u0 = __float_as_uint(v.x), u1 = __float_as_uint(v.y);
    uint32_t u2 = __float_as_uint(v.z), u3 = __float_as_uint(v.w);
    hi.x = (u0 >> 16) | (u1 & 0xFFFF0000u);
    hi.y = (u2 >> 16) | (u3 & 0xFFFF0000u);
    float l0 = v.x - __uint_as_float(u0 & 0xFFFF0000u);
    float l1 = v.y - __uint_as_float(u1 & 0xFFFF0000u);
    float l2 = v.z - __uint_as_float(u2 & 0xFFFF0000u);
    float l3 = v.w - __uint_as_float(u3 & 0xFFFF0000u);
    __nv_bfloat162 p01 = __floats2bfloat162_rn(l0, l1);
    __nv_bfloat162 p23 = __floats2bfloat162_rn(l2, l3);
    lo.x = *reinterpret_cast<uint32_t*>(&p01);
    lo.y = *reinterpret_cast<uint32_t*>(&p23);
}

__device__ __forceinline__ float norm_factor(float ssq_part, float scale) {
    float ssq = ssq_part;
    #pragma unroll
    for (int o = 16; o > 0; o >>= 1) ssq += __shfl_xor_sync(0xffffffffu, ssq, o);
    __shared__ float ws[8];
    int w = threadIdx.x >> 5, l = threadIdx.x & 31;
    if (l == 0) ws[w] = ssq;
    __syncthreads();
    if (w == 0) {
        float s = (l < 8) ? ws[l] : 0.0f;
        #pragma unroll
        for (int o = 4; o > 0; o >>= 1) s += __shfl_xor_sync(0xffffffffu, s, o);
        if (l == 0) ws[0] = s;
    }
    __syncthreads();
    return scale / fmaxf(sqrtf(ws[0]), 1e-5f);
}

// pack one float4 (local row rl in 16-row frag block, k-base klb multiple of 4)
__device__ __forceinline__ void store_frag(char* oh, char* ol, size_t fragbase,
                                           int rl, int klb, uint2 hi, uint2 lo) {
    int lane = ((rl & 7) << 2) | ((klb & 7) >> 1);
    int reg  = (rl >> 3) + 2 * (klb >> 3);
    size_t b = fragbase + lane * 16 + reg * 4;
    *(uint32_t*)(oh + b)      = hi.x;
    *(uint32_t*)(oh + b + 16) = hi.y;
    *(uint32_t*)(ol + b)      = lo.x;
    *(uint32_t*)(ol + b + 16) = lo.y;
}

// ===========================================================================
// scalenorm_x: x[4096,1024] -> packed frag hi/lo (frag idx = bm*64 + bk)
// ===========================================================================
__global__ __launch_bounds__(256) void scalenorm_x(
    const float* __restrict__ in, const float* __restrict__ scale_p,
    __nv_bfloat16* __restrict__ oh, __nv_bfloat16* __restrict__ ol)
{
    int r = blockIdx.x, t = threadIdx.x;
    float4 f = ((const float4*)in)[(size_t)r * 256 + t];
    float fac = norm_factor(f.x*f.x + f.y*f.y + f.z*f.z + f.w*f.w, scale_p[0]);
    f.x *= fac; f.y *= fac; f.z *= fac; f.w *= fac;
    uint2 hi, lo;
    split_f4(f, hi, lo);
    int bm = r >> 4, rl = r & 15;
    int bk = t >> 2, klb = 4 * (t & 3);
    store_frag((char*)oh, (char*)ol, (size_t)(bm * 64 + bk) * 512, rl, klb, hi, lo);
}

// ===========================================================================
// scalenorm_qkv: raw-view group semantics.
// Row r = b*2048 + t_seq, col d = 4*t .. 4*t+3.
//   g = b*16 + (t_seq >> 7);  s = (t_seq & 127)*16 + (d >> 6);  e = d & 63
// z=0: q -> packed frags per group   (bm = s>>4 = r&127, rl = s&15 = t>>4,
//                                     bk = (e0>>4) = (t>>2)&3, klb = e0&15)
// z=1: k -> group-slab row-major [g][2048][64] bf16 hi/lo
// z=2: v normalized in place (fp32)
// ===========================================================================
__global__ __launch_bounds__(256) void scalenorm_qkv(
    const float* __restrict__ q, const float* __restrict__ k,
    float* __restrict__ v, const float* __restrict__ scale_p,
    __nv_bfloat16* __restrict__ qh, __nv_bfloat16* __restrict__ ql,
    __nv_bfloat16* __restrict__ kh, __nv_bfloat16* __restrict__ kl)
{
    int z = blockIdx.y, r = blockIdx.x, t = threadIdx.x;
    const float* in = (z == 0) ? q : (z == 1) ? k : v;
    float4 f = ((const float4*)in)[(size_t)r * 256 + t];
    float fac = norm_factor(f.x*f.x + f.y*f.y + f.z*f.z + f.w*f.w, scale_p[0]);
    f.x *= fac; f.y *= fac; f.z *= fac; f.w *= fac;

    if (z == 2) { ((float4*)v)[(size_t)r * 256 + t] = f; return; }
    uint2 hi, lo;
    split_f4(f, hi, lo);
    int g = ((r >> 11) << 4) + ((r & 2047) >> 7);
    if (z == 1) {
        int s  = (r & 127) * 16 + (t >> 4);
        int e0 = 4 * (t & 15);
        size_t off = (size_t)g * 131072 + (size_t)s * 64 + e0;   // elements
        *(uint2*)((char*)kh + off * 2) = hi;
        *(uint2*)((char*)kl + off * 2) = lo;
    } else {
        int bm = r & 127;
        int rl = t >> 4;
        int bk = (t >> 2) & 3;
        int klb = 4 * (t & 3);
        size_t base = (size_t)g * 262144 + (size_t)(bm * 4 + bk) * 512; // bytes
        store_frag((char*)qh, (char*)ql, base, rl, klb, hi, lo);
    }
}

// ===========================================================================
// weight split: 3 x [1024x1024] -> concatenated row-major bf16 hi/lo
// ===========================================================================
__global__ __launch_bounds__(256) void wsplit(
    const float* __restrict__ w0, const float* __restrict__ w1,
    const float* __restrict__ w2,
    __nv_bfloat16* __restrict__ wh, __nv_bfloat16* __restrict__ wl)
{
    size_t idx = ((size_t)blockIdx.x * 256 + threadIdx.x) * 4;
    int which = (int)(idx >> 20);
    const float* src = (which == 0) ? w0 : (which == 1) ? w1 : w2;
    float4 f = *(const float4*)(src + (idx & 1048575));
    uint2 hi, lo;
    split_f4(f, hi, lo);
    *(uint2*)((char*)wh + idx * 2) = hi;
    *(uint2*)((char*)wl + idx * 2) = lo;
}

// ===========================================================================
// V^T + hi/lo split:  flat slab v+g*131072 as [2048][64] -> [g][64][2048]
// ===========================================================================
__global__ __launch_bounds__(256) void vt_convert(
    const float* __restrict__ v,
    __nv_bfloat16* __restrict__ vh, __nv_bfloat16* __restrict__ vl)
{
    int g  = blockIdx.z;
    int k0 = blockIdx.x * 64;
    const float* vg = v + (size_t)g * GRP_STRIDE;
    __shared__ float sm[64][68];
    int t = threadIdx.x;
    int kr = t >> 2, f4 = (t & 3) * 4;
    const float4* rp = (const float4*)(vg + (size_t)(k0 + kr) * DK);
    #pragma unroll
    for (int i = 0; i < 4; i++) {
        float4 f = rp[f4 + i];
        *(float4*)&sm[kr][(f4 + i) * 4] = f;
    }
    __syncthreads();
    int n = t >> 2;
    size_t ob = (size_t)g * (DK * TSEQ) + (size_t)n * TSEQ + k0;
    #pragma unroll
    for (int j = 0; j < 4; j++) {
        int kk = (t & 3) * 16 + j * 4;
        float4 f = make_float4(sm[kk+0][n], sm[kk+1][n], sm[kk+2][n], sm[kk+3][n]);
        uint2 hi, lo;
        split_f4(f, hi, lo);
        *(uint2*)((char*)vh + (ob + kk) * 2) = hi;
        *(uint2*)((char*)vl + (ob + kk) * 2) = lo;
    }
}

// ===========================================================================
// gemm_pa: C = alpha*(A @ B^T) + bias.  A = packed frags (direct LDG),
// B = row-major bf16 hi/lo via swizzled double-buffered smem.
// BM=128, BN=128, BK=32; 8 warps 2(m)x4(n), warp tile 64x32.
// mode 0: proj batch (z: wq/wk/wv).  mode 1: QK batch (z = group, slabs).
// ===========================================================================
#define GP_SMEM 32768

__global__ __launch_bounds__(256) void gemm_pa(
    int mode,
    const __nv_bfloat16* __restrict__ Ah, const __nv_bfloat16* __restrict__ Al,
    const __nv_bfloat16* __restrict__ Bh, const __nv_bfloat16* __restrict__ Bl,
    const float* __restrict__ bias0, const float* __restrict__ bias1,
    const float* __restrict__ bias2,
    float* __restrict__ C0, float* __restrict__ C1, float* __restrict__ C2,
    int fpr, int ldb, int ldc, int K, float alpha)
{
    extern __shared__ char smx[];
    uint32_t sbase = smem_u32(smx);

    const float* bias;
    float* C;
    int z = blockIdx.z;
    if (mode == 0) {
        Bh += (size_t)z * 1048576;  Bl += (size_t)z * 1048576;
        bias = (z == 0) ? bias0 : (z == 1) ? bias1 : bias2;
        C    = (z == 0) ? C0    : (z == 1) ? C1    : C2;
    } else {
        Ah += (size_t)z * 131072;   Al += (size_t)z * 131072;
        Bh += (size_t)z * 131072;   Bl += (size_t)z * 131072;
        bias = nullptr;
        C = C0 + (size_t)z * (size_t)ATTN_PER_G;
    }
    int rowBase = blockIdx.y * 128, colBase = blockIdx.x * 128;
    int tid = threadIdx.x, lane = tid & 31, wid = tid >> 5;
    int wm = wid >> 2, wn = wid & 3;

    // B loader
    int br = tid >> 1, bhalf = tid & 1;
    const __nv_bfloat16* BhP = Bh + (size_t)(colBase + br) * ldb + bhalf * 16;
    const __nv_bfloat16* BlP = Bl + (size_t)(colBase + br) * ldb + bhalf * 16;
    uint32_t swz = (br >> 1) & 3;
    uint32_t sw0 = br * 64 + (((2u * bhalf)     ^ swz) << 4);
    uint32_t sw1 = br * 64 + (((2u * bhalf + 1) ^ swz) << 4);

    const char* AhB = (const char*)Ah;
    const char* AlB = (const char*)Al;
    int frow0 = (rowBase >> 4) + wm * 4;

    // prologue: B chunk 0 -> stage 0
    uint4 pbh0 = *(const uint4*)BhP, pbh1 = *(const uint4*)(BhP + 8);
    uint4 pbl0 = *(const uint4*)BlP, pbl1 = *(const uint4*)(BlP + 8);
    *(uint4*)(smx + sw0)        = pbh0;
    *(uint4*)(smx + sw1)        = pbh1;
    *(uint4*)(smx + 8192 + sw0) = pbl0;
    *(uint4*)(smx + 8192 + sw1) = pbl1;
    __syncthreads();

    float acc[4][4][4];
    #pragma unroll
    for (int a = 0; a < 4; a++)
        #pragma unroll
        for (int b = 0; b < 4; b++)
            #pragma unroll
            for (int r = 0; r < 4; r++) acc[a][b][r] = 0.0f;

    int NC = K >> 5;
    for (int c = 0; c < NC; c++) {
        if (c + 1 < NC) {
            const __nv_bfloat16* ph = BhP + (c + 1) * 32;
            const __nv_bfloat16* pl = BlP + (c + 1) * 32;
            pbh0 = *(const uint4*)ph;  pbh1 = *(const uint4*)(ph + 8);
            pbl0 = *(const uint4*)pl;  pbl1 = *(const uint4*)(pl + 8);
        }
        // A fragments: direct LDG.128 (L2-resident)
        uint4 aH[2][4], aL[2][4];
        #pragma unroll
        for (int kk = 0; kk < 2; kk++)
            #pragma unroll
            for (int mt = 0; mt < 4; mt++) {
                size_t fo = ((size_t)(frow0 + mt) * fpr + (c * 2 + kk)) * 512
                          + lane * 16;
                aH[kk][mt] = *(const uint4*)(AhB + fo);
                aL[kk][mt] = *(const uint4*)(AlB + fo);
            }
        uint32_t stg = sbase + (c & 1) * 16384;
        #pragma unroll
        for (int kk = 0; kk < 2; kk++) {
            uint32_t bh[2][4], bl[2][4];
            #pragma unroll
            for (int np = 0; np < 2; np++) {
                int r = wn * 32 + np * 16 + ((lane >> 4) << 3) + (lane & 7);
                int c16 = kk * 2 + ((lane >> 3) & 1);
                uint32_t off = r * 64 + (((uint32_t)c16 ^ ((r >> 1) & 3)) << 4);
                ldsm4(bh[np], stg + off);
                ldsm4(bl[np], stg + 8192 + off);
            }
            #pragma unroll
            for (int mt = 0; mt < 4; mt++) {
                const uint32_t* ah = (const uint32_t*)&aH[kk][mt];
                const uint32_t* al = (const uint32_t*)&aL[kk][mt];
                #pragma unroll
                for (int nt = 0; nt < 4; nt++) {
                    const uint32_t* ph = &bh[nt >> 1][(nt & 1) * 2];
                    const uint32_t* pl = &bl[nt >> 1][(nt & 1) * 2];
                    mma16816(acc[mt][nt], ah, ph);
                    mma16816(acc[mt][nt], ah, pl);
                    mma16816(acc[mt][nt], al, ph);
                }
            }
        }
        if (c + 1 < NC) {
            char* s = smx + ((c + 1) & 1) * 16384;
            *(uint4*)(s + sw0)        = pbh0;
            *(uint4*)(s + sw1)        = pbh1;
            *(uint4*)(s + 8192 + sw0) = pbl0;
            *(uint4*)(s + 8192 + sw1) = pbl1;
        }
        __syncthreads();
    }

    // epilogue
    int r0 = rowBase + wm * 64 + (lane >> 2);
    int c0 = colBase + wn * 32 + (lane & 3) * 2;
    #pragma unroll
    for (int nt = 0; nt < 4; nt++) {
        int col = c0 + nt * 8;
        float b0 = 0.0f, b1 = 0.0f;
        if (bias) { b0 = bias[col]; b1 = bias[col + 1]; }
        #pragma unroll
        for (int mt = 0; mt < 4; mt++) {
            int row = r0 + mt * 16;
            *(float2*)(C + (size_t)row * ldc + col) =
                make_float2(acc[mt][nt][0] * alpha + b0,
                            acc[mt][nt][1] * alpha + b1);
            *(float2*)(C + (size_t)(row + 8) * ldc + col) =
                make_float2(acc[mt][nt][2] * alpha + b0,
                            acc[mt][nt][3] * alpha + b1);
        }
    }
}

// ===========================================================================
// PV: O[g] = attn[g] @ V^T-tiles, scatter epilogue (flat-slab semantics)
// ===========================================================================
#define PST 30720
#define PV_SMEM (2 * PST)

__global__ __launch_bounds__(256, 1) void pv_mma(
    const float* __restrict__ P,
    const __nv_bfloat16* __restrict__ vh, const __nv_bfloat16* __restrict__ vl,
    float* __restrict__ Out)
{
    extern __shared__ char smx[];
    uint32_t sbase = smem_u32(smx);

    int g = blockIdx.z;
    int rowBase = blockIdx.x * 128;
    const float* Pg = P + (size_t)g * ATTN_PER_G;
    const __nv_bfloat16* vhg = vh + (size_t)g * (DK * TSEQ);
    const __nv_bfloat16* vlg = vl + (size_t)g * (DK * TSEQ);

    int tid = threadIdx.x, lane = tid & 31, wid = tid >> 5;
    int wm = wid >> 1, wn = wid & 1;
    int lr = tid >> 1, lc = (tid & 1) * 16;
    int rowoff = lr * 80;

    const float* Abase = Pg + (size_t)(rowBase + lr) * TSEQ + lc;
    int bn = tid >> 2, bch = tid & 3;
    const __nv_bfloat16* BhBase = vhg + (size_t)bn * TSEQ + bch * 8;
    const __nv_bfloat16* BlBase = vlg + (size_t)bn * TSEQ + bch * 8;
    int boff = bn * 80 + bch * 16;

    float4 ra[4];
    uint4 rbh, rbl;
    #pragma unroll
    for (int i = 0; i < 4; i++) ra[i] = *(const float4*)(Abase + 4 * i);
    rbh = *(const uint4*)BhBase;
    rbl = *(const uint4*)BlBase;
    {
        char* s = smx;
        #pragma unroll
        for (int i = 0; i < 4; i++) {
            uint2 h, l;
            split_f4(ra[i], h, l);
            *(uint2*)(s +     0 + rowoff + (lc + 4 * i) * 2) = h;
            *(uint2*)(s + 10240 + rowoff + (lc + 4 * i) * 2) = l;
        }
        *(uint4*)(s + 20480 + boff) = rbh;
        *(uint4*)(s + 25600 + boff) = rbl;
    }
    __syncthreads();

    float acc[2][4][4];
    #pragma unroll
    for (int a = 0; a < 2; a++)
        #pragma unroll
        for (int b = 0; b < 4; b++)
            #pragma unroll
            for (int r = 0; r < 4; r++) acc[a][b][r] = 0.0f;

    const int NC = TSEQ / 32;
    for (int c = 0; c < NC; c++) {
        if (c + 1 < NC) {
            const float* ap = Abase + (c + 1) * 32;
            #pragma unroll
            for (int i = 0; i < 4; i++) ra[i] = *(const float4*)(ap + 4 * i);
            rbh = *(const uint4*)(BhBase + (c + 1) * 32);
            rbl = *(const uint4*)(BlBase + (c + 1) * 32);
        }
        uint32_t s0 = sbase + (c & 1) * PST;
        #pragma unroll
        for (int kk = 0; kk < 2; kk++) {
            uint32_t ah[2][4], al[2][4];
            #pragma unroll
            for (int mt = 0; mt < 2; mt++) {
                int row = wm * 32 + mt * 16 + (lane & 15);
                uint32_t off = row * 80 + kk * 32 + (lane >> 4) * 16;
                ldsm4(ah[mt], s0 + off);
                ldsm4(al[mt], s0 + 10240 + off);
            }
            uint32_t bh[2][4], bl[2][4];
            #pragma unroll
            for (int np = 0; np < 2; np++) {
                int nrow = wn * 32 + np * 16 + ((lane >> 4) << 3) + (lane & 7);
                uint32_t off = nrow * 80 + kk * 32 + ((lane >> 3) & 1) * 16;
                ldsm4(bh[np], s0 + 20480 + off);
                ldsm4(bl[np], s0 + 25600 + off);
            }
            #pragma unroll
            for (int mt = 0; mt < 2; mt++)
                #pragma unroll
                for (int nt = 0; nt < 4; nt++) {
                    const uint32_t* ph = &bh[nt >> 1][(nt & 1) * 2];
                    const uint32_t* pl = &bl[nt >> 1][(nt & 1) * 2];
                    mma16816(acc[mt][nt], ah[mt], ph);
                    mma16816(acc[mt][nt], ah[mt], pl);
                    mma16816(acc[mt][nt], al[mt], ph);
                }
        }
        if (c + 1 < NC) {
            char* s = smx + ((c + 1) & 1) * PST;
            #pragma unroll
            for (int i = 0; i < 4; i++) {
                uint2 h, l;
                split_f4(ra[i], h, l);
                *(uint2*)(s +     0 + rowoff + (lc + 4 * i) * 2) = h;
                *(uint2*)(s + 10240 + rowoff + (lc + 4 * i) * 2) = l;
            }
            *(uint4*)(s + 20480 + boff) = rbh;
            *(uint4*)(s + 25600 + boff) = rbl;
        }
        __syncthreads();
    }

    int b  = g >> 4;
    int gg = g & 15;
    float* ob = Out + (size_t)b * 2097152;
    int rr = rowBase + wm * 32 + (lane >> 2);
    int e0 = wn * 32 + (lane & 3) * 2;
    #pragma unroll
    for (int mt = 0; mt < 2; mt++) {
        #pragma unroll
        for (int half = 0; half < 2; half++) {
            int s   = rr + mt * 16 + half * 8;
            int thi = s >> 10;
            int d   = s & 1023;
            #pragma unroll
            for (int nt = 0; nt < 4; nt++) {
                int e  = e0 + nt * 8;
                int t0 = gg * 128 + 2 * e + thi;
                int t1 = gg * 128 + 2 * (e + 1) + thi;
                ob[(size_t)t0 * 1024 + d] = acc[mt][nt][half * 2 + 0];
                ob[(size_t)t1 * 1024 + d] = acc[mt][nt][half * 2 + 1];
            }
        }
    }
}

// ===========================================================================
// Row softmax in place
// ===========================================================================
__global__ __launch_bounds__(256) void softmax_kernel(float* __restrict__ attn)
{
    size_t row = blockIdx.x;
    float4* p = (float4*)attn + row * (TSEQ / 4);
    int tid = threadIdx.x;

    float4 a = p[tid];
    float4 b = p[tid + 256];

    float m = fmaxf(fmaxf(fmaxf(a.x, a.y), fmaxf(a.z, a.w)),
                    fmaxf(fmaxf(b.x, b.y), fmaxf(b.z, b.w)));
    #pragma unroll
    for (int o = 16; o > 0; o >>= 1) m = fmaxf(m, __shfl_xor_sync(0xffffffffu, m, o));

    __shared__ float ws[8];
    int w = tid >> 5, l = tid & 31;
    if (l == 0) ws[w] = m;
    __syncthreads();
    if (w == 0) {
        float s = (l < 8) ? ws[l] : -3.4e38f;
        #pragma unroll
        for (int o = 4; o > 0; o >>= 1) s = fmaxf(s, __shfl_xor_sync(0xffffffffu, s, o));
        if (l == 0) ws[0] = s;
    }
    __syncthreads();
    m = ws[0];
    __syncthreads();

    a.x = __expf(a.x - m); a.y = __expf(a.y - m);
    a.z = __expf(a.z - m); a.w = __expf(a.w - m);
    b.x = __expf(b.x - m); b.y = __expf(b.y - m);
    b.z = __expf(b.z - m); b.w = __expf(b.w - m);

    float ssum = a.x + a.y + a.z + a.w + b.x + b.y + b.z + b.w;
    #pragma unroll
    for (int o = 16; o > 0; o >>= 1) ssum += __shfl_xor_sync(0xffffffffu, ssum, o);
    if (l == 0) ws[w] = ssum;
    __syncthreads();
    if (w == 0) {
        float s = (l < 8) ? ws[l] : 0.0f;
        #pragma unroll
        for (int o = 4; o > 0; o >>= 1) s += __shfl_xor_sync(0xffffffffu, s, o);
        if (l == 0) ws[0] = s;
    }
    __syncthreads();
    float inv = 1.0f / ws[0];

    a.x *= inv; a.y *= inv; a.z *= inv; a.w *= inv;
    b.x *= inv; b.y *= inv; b.z *= inv; b.w *= inv;
    p[tid]       = a;
    p[tid + 256] = b;
}

// ===========================================================================
// kernel_launch
// ===========================================================================
extern "C" void kernel_launch(void* const* d_in, const int* in_sizes, int n_in,
                              void* d_out, int out_size)
{
    const float* x  = (const float*)d_in[0];
    const float* sc = (const float*)d_in[1];
    const float* wq = (const float*)d_in[2];
    const float* bq = (const float*)d_in[3];
    const float* wk = (const float*)d_in[4];
    const float* bk = (const float*)d_in[5];
    const float* wv = (const float*)d_in[6];
    const float* bv = (const float*)d_in[7];

    float* out  = (float*)d_out;
    float* attn = out + OUT_ELEMS;

    float *q, *k, *v;
    __nv_bfloat16 *xh, *xl, *qh, *ql, *kh, *kl, *wh, *wl, *vh, *vl;
    cudaGetSymbolAddress((void**)&q,  g_q);
    cudaGetSymbolAddress((void**)&k,  g_k);
    cudaGetSymbolAddress((void**)&v,  g_v);
    cudaGetSymbolAddress((void**)&xh, g_xh);
    cudaGetSymbolAddress((void**)&xl, g_xl);
    cudaGetSymbolAddress((void**)&qh, g_qh);
    cudaGetSymbolAddress((void**)&ql, g_ql);
    cudaGetSymbolAddress((void**)&kh, g_kh);
    cudaGetSymbolAddress((void**)&kl, g_kl);
    cudaGetSymbolAddress((void**)&wh, g_wh);
    cudaGetSymbolAddress((void**)&wl, g_wl);
    cudaGetSymbolAddress((void**)&vh, g_vh);
    cudaGetSymbolAddress((void**)&vl, g_vl);

    cudaFuncSetAttribute(gemm_pa, cudaFuncAttributeMaxDynamicSharedMemorySize, GP_SMEM);
    cudaFuncSetAttribute(pv_mma,  cudaFuncAttributeMaxDynamicSharedMemorySize, PV_SMEM);

    // 1) normalize x -> packed frags; split weights
    scalenorm_x<<<ROWS, 256>>>(x, sc, xh, xl);
    wsplit<<<3072, 256>>>(wq, wk, wv, wh, wl);

    // 2) projections: one batched launch (z = q/k/v)
    gemm_pa<<<dim3(8, 32, 3), 256, GP_SMEM>>>(
        0, xh, xl, wh, wl, bq, bk, bv, q, k, v,
        64, DMODEL, DMODEL, DMODEL, 1.0f);

    // 3) scale_norm q/k/v (raw-view group packing)
    scalenorm_qkv<<<dim3(ROWS, 3), 256>>>(q, k, v, sc, qh, ql, kh, kl);

    // 3b) V^T hi/lo split
    vt_convert<<<dim3(TSEQ / 64, 1, NGRP), 256>>>(v, vh, vl);

    // 4) S = Q K^T / 8 into attn region (z = group, flat slabs, ldb = 64)
    gemm_pa<<<dim3(16, 16, NGRP), 256, GP_SMEM>>>(
        1, qh, ql, kh, kl, nullptr, nullptr, nullptr, attn, nullptr, nullptr,
        4, DK, TSEQ, DK, 0.125f);

    // 5) softmax in place
    softmax_kernel<<<NGRP * TSEQ, 256>>>(attn);

    // 6) O = attn @ V with scatter epilogue
    pv_mma<<<dim3(TSEQ / 128, 1, NGRP), 256, PV_SMEM>>>(attn, vh, vl, out);
}

// round 7
// speedup vs baseline: 1.6398x; 1.6398x over previous
#include <cuda_runtime.h>
#include <cuda_bf16.h>
#include <math.h>
#include <stdint.h>

#define ROWS   4096
#define DMODEL 1024
#define TSEQ   2048
#define DK     64
#define NGRP   32
#define OUT_ELEMS 4194304
#define ATTN_PER_G 4194304
#define GRP_STRIDE 131072

// Scratch
__device__ float g_q[ROWS * DMODEL];
__device__ float g_k[ROWS * DMODEL];
__device__ float g_v[ROWS * DMODEL];
__device__ __nv_bfloat16 g_xh[ROWS * DMODEL], g_xl[ROWS * DMODEL];   // row-major
__device__ __nv_bfloat16 g_qh[ROWS * DMODEL], g_ql[ROWS * DMODEL];   // group slabs [g][2048][64]
__device__ __nv_bfloat16 g_kh[ROWS * DMODEL], g_kl[ROWS * DMODEL];   // group slabs
__device__ __nv_bfloat16 g_wh[3 * DMODEL * DMODEL], g_wl[3 * DMODEL * DMODEL];
__device__ __nv_bfloat16 g_vh[NGRP * DK * TSEQ], g_vl[NGRP * DK * TSEQ];

// ===========================================================================
__device__ __forceinline__ uint32_t smem_u32(const void* p) {
    uint32_t a;
    asm("{ .reg .u64 t; cvta.to.shared.u64 t, %1; cvt.u32.u64 %0, t; }"
        : "=r"(a) : "l"(p));
    return a;
}

__device__ __forceinline__ void ldsm4(uint32_t* r, uint32_t addr) {
    asm volatile("ldmatrix.sync.aligned.m8n8.x4.shared.b16 {%0,%1,%2,%3}, [%4];"
                 : "=r"(r[0]), "=r"(r[1]), "=r"(r[2]), "=r"(r[3]) : "r"(addr));
}

__device__ __forceinline__ void mma16816(float* c, const uint32_t* a,
                                         const uint32_t* b) {
    asm volatile(
        "mma.sync.aligned.m16n8k16.row.col.f32.bf16.bf16.f32 "
        "{%0,%1,%2,%3}, {%4,%5,%6,%7}, {%8,%9}, {%0,%1,%2,%3};"
        : "+f"(c[0]), "+f"(c[1]), "+f"(c[2]), "+f"(c[3])
        : "r"(a[0]), "r"(a[1]), "r"(a[2]), "r"(a[3]), "r"(b[0]), "r"(b[1]));
}

__device__ __forceinline__ void cpa16(uint32_t dst, const void* src) {
    asm volatile("cp.async.cg.shared.global [%0], [%1], 16;"
                 :: "r"(dst), "l"(src));
}
#define CP_COMMIT() asm volatile("cp.async.commit_group;" ::: "memory")
#define CP_WAIT(n)  asm volatile("cp.async.wait_group %0;" :: "n"(n) : "memory")

__device__ __forceinline__ void split_f4(float4 v, uint2& hi, uint2& lo) {
    uint32_t u0 = __float_as_uint(v.x), u1 = __float_as_uint(v.y);
    uint32_t u2 = __float_as_uint(v.z), u3 = __float_as_uint(v.w);
    hi.x = (u0 >> 16) | (u1 & 0xFFFF0000u);
    hi.y = (u2 >> 16) | (u3 & 0xFFFF0000u);
    float l0 = v.x - __uint_as_float(u0 & 0xFFFF0000u);
    float l1 = v.y - __uint_as_float(u1 & 0xFFFF0000u);
    float l2 = v.z - __uint_as_float(u2 & 0xFFFF0000u);
    float l3 = v.w - __uint_as_float(u3 & 0xFFFF0000u);
    __nv_bfloat162 p01 = __floats2bfloat162_rn(l0, l1);
    __nv_bfloat162 p23 = __floats2bfloat162_rn(l2, l3);
    lo.x = *reinterpret_cast<uint32_t*>(&p01);
    lo.y = *reinterpret_cast<uint32_t*>(&p23);
}

__device__ __forceinline__ float norm_factor(float ssq_part, float scale) {
    float ssq = ssq_part;
    #pragma unroll
    for (int o = 16; o > 0; o >>= 1) ssq += __shfl_xor_sync(0xffffffffu, ssq, o);
    __shared__ float ws[8];
    int w = threadIdx.x >> 5, l = threadIdx.x & 31;
    if (l == 0) ws[w] = ssq;
    __syncthreads();
    if (w == 0) {
        float s = (l < 8) ? ws[l] : 0.0f;
        #pragma unroll
        for (int o = 4; o > 0; o >>= 1) s += __shfl_xor_sync(0xffffffffu, s, o);
        if (l == 0) ws[0] = s;
    }
    __syncthreads();
    return scale / fmaxf(sqrtf(ws[0]), 1e-5f);
}

// ===========================================================================
// scalenorm_x: x[4096,1024] -> row-major bf16 hi/lo
// ===========================================================================
__global__ __launch_bounds__(256) void scalenorm_x(
    const float* __restrict__ in, const float* __restrict__ scale_p,
    __nv_bfloat16* __restrict__ oh, __nv_bfloat16* __restrict__ ol)
{
    int r = blockIdx.x, t = threadIdx.x;
    float4 f = ((const float4*)in)[(size_t)r * 256 + t];
    float fac = norm_factor(f.x*f.x + f.y*f.y + f.z*f.z + f.w*f.w, scale_p[0]);
    f.x *= fac; f.y *= fac; f.z *= fac; f.w *= fac;
    uint2 hi, lo;
    split_f4(f, hi, lo);
    size_t off = (size_t)r * 1024 + t * 4;
    *(uint2*)((char*)oh + off * 2) = hi;
    *(uint2*)((char*)ol + off * 2) = lo;
}

// ===========================================================================
// scalenorm_qkv: raw-view group slabs.
//   g = b*16 + (t_seq>>7);  s = (t_seq&127)*16 + (d>>6);  e = d&63
// z=0: q -> slab [g][2048][64] hi/lo;  z=1: k -> slab;  z=2: v in place
// ===========================================================================
__global__ __launch_bounds__(256) void scalenorm_qkv(
    const float* __restrict__ q, const float* __restrict__ k,
    float* __restrict__ v, const float* __restrict__ scale_p,
    __nv_bfloat16* __restrict__ qh, __nv_bfloat16* __restrict__ ql,
    __nv_bfloat16* __restrict__ kh, __nv_bfloat16* __restrict__ kl)
{
    int z = blockIdx.y, r = blockIdx.x, t = threadIdx.x;
    const float* in = (z == 0) ? q : (z == 1) ? k : v;
    float4 f = ((const float4*)in)[(size_t)r * 256 + t];
    float fac = norm_factor(f.x*f.x + f.y*f.y + f.z*f.z + f.w*f.w, scale_p[0]);
    f.x *= fac; f.y *= fac; f.z *= fac; f.w *= fac;

    if (z == 2) { ((float4*)v)[(size_t)r * 256 + t] = f; return; }
    uint2 hi, lo;
    split_f4(f, hi, lo);
    // slab offset: group-flat view is just contiguous memory, so offset is
    // identical to row-major: g*131072 + s*64 + e == r*1024 + 4t.
    size_t off = (size_t)r * 1024 + t * 4;
    if (z == 1) {
        *(uint2*)((char*)kh + off * 2) = hi;
        *(uint2*)((char*)kl + off * 2) = lo;
    } else {
        *(uint2*)((char*)qh + off * 2) = hi;
        *(uint2*)((char*)ql + off * 2) = lo;
    }
}

// ===========================================================================
// weight split
// ===========================================================================
__global__ __launch_bounds__(256) void wsplit(
    const float* __restrict__ w0, const float* __restrict__ w1,
    const float* __restrict__ w2,
    __nv_bfloat16* __restrict__ wh, __nv_bfloat16* __restrict__ wl)
{
    size_t idx = ((size_t)blockIdx.x * 256 + threadIdx.x) * 4;
    int which = (int)(idx >> 20);
    const float* src = (which == 0) ? w0 : (which == 1) ? w1 : w2;
    float4 f = *(const float4*)(src + (idx & 1048575));
    uint2 hi, lo;
    split_f4(f, hi, lo);
    *(uint2*)((char*)wh + idx * 2) = hi;
    *(uint2*)((char*)wl + idx * 2) = lo;
}

// ===========================================================================
// V^T + hi/lo split
// ===========================================================================
__global__ __launch_bounds__(256) void vt_convert(
    const float* __restrict__ v,
    __nv_bfloat16* __restrict__ vh, __nv_bfloat16* __restrict__ vl)
{
    int g  = blockIdx.z;
    int k0 = blockIdx.x * 64;
    const float* vg = v + (size_t)g * GRP_STRIDE;
    __shared__ float sm[64][68];
    int t = threadIdx.x;
    int kr = t >> 2, f4 = (t & 3) * 4;
    const float4* rp = (const float4*)(vg + (size_t)(k0 + kr) * DK);
    #pragma unroll
    for (int i = 0; i < 4; i++) {
        float4 f = rp[f4 + i];
        *(float4*)&sm[kr][(f4 + i) * 4] = f;
    }
    __syncthreads();
    int n = t >> 2;
    size_t ob = (size_t)g * (DK * TSEQ) + (size_t)n * TSEQ + k0;
    #pragma unroll
    for (int j = 0; j < 4; j++) {
        int kk = (t & 3) * 16 + j * 4;
        float4 f = make_float4(sm[kk+0][n], sm[kk+1][n], sm[kk+2][n], sm[kk+3][n]);
        uint2 hi, lo;
        split_f4(f, hi, lo);
        *(uint2*)((char*)vh + (ob + kk) * 2) = hi;
        *(uint2*)((char*)vl + (ob + kk) * 2) = lo;
    }
}

// ===========================================================================
// gemm_bb: C = alpha*(A @ B^T) + bias.  A,B pre-split bf16 hi/lo row-major
// (K-contiguous).  BM=128, BN=128, BK=32, 8 warps 2(m)x4(n), warp 64x32.
// cp.async 3-stage pipeline; 64B-row XOR-swizzled smem; 2 CTAs/SM.
// stage: Ah 8K | Al 8K | Bh 8K | Bl 8K = 32KB; 3 stages = 96KB.
// mode 0: proj (z: wq/wk/wv).  mode 1: QK (z = group slabs).
// ===========================================================================
#define NSTAGE  3
#define STG_SZ  32768
#define GB_SMEM (NSTAGE * STG_SZ)

__global__ __launch_bounds__(256, 2) void gemm_bb(
    int mode,
    const __nv_bfloat16* __restrict__ Ah, const __nv_bfloat16* __restrict__ Al,
    const __nv_bfloat16* __restrict__ Bh, const __nv_bfloat16* __restrict__ Bl,
    const float* __restrict__ bias0, const float* __restrict__ bias1,
    const float* __restrict__ bias2,
    float* __restrict__ C0, float* __restrict__ C1, float* __restrict__ C2,
    int lda, int ldb, int ldc, int K, float alpha)
{
    extern __shared__ char smx[];
    uint32_t sbase = smem_u32(smx);

    const float* bias;
    float* C;
    int z = blockIdx.z;
    if (mode == 0) {
        Bh += (size_t)z * 1048576;  Bl += (size_t)z * 1048576;
        bias = (z == 0) ? bias0 : (z == 1) ? bias1 : bias2;
        C    = (z == 0) ? C0    : (z == 1) ? C1    : C2;
    } else {
        Ah += (size_t)z * 131072;   Al += (size_t)z * 131072;
        Bh += (size_t)z * 131072;   Bl += (size_t)z * 131072;
        bias = nullptr;
        C = C0 + (size_t)z * (size_t)ATTN_PER_G;
    }
    int rowBase = blockIdx.y * 128, colBase = blockIdx.x * 128;
    int tid = threadIdx.x, lane = tid & 31, wid = tid >> 5;
    int wm = wid >> 2, wn = wid & 3;

    // loader geometry: 128 rows, 2 threads/row, each thread 2x16B per buffer
    int lr = tid >> 1, half = tid & 1;
    uint32_t swz = (lr >> 1) & 3;
    uint32_t d0 = lr * 64 + (((2u * half + 0) ^ swz) << 4);
    uint32_t d1 = lr * 64 + (((2u * half + 1) ^ swz) << 4);
    const char* aSrcH = (const char*)(Ah + (size_t)(rowBase + lr) * lda + half * 16);
    const char* aSrcL = (const char*)(Al + (size_t)(rowBase + lr) * lda + half * 16);
    const char* bSrcH = (const char*)(Bh + (size_t)(colBase + lr) * ldb + half * 16);
    const char* bSrcL = (const char*)(Bl + (size_t)(colBase + lr) * ldb + half * 16);

    int NC = K >> 5;

    // issue one chunk's 8 cp.asyncs into stage s
    auto issue = [&](int c, int s) {
        uint32_t st = sbase + s * STG_SZ;
        size_t ko = (size_t)c * 64;   // bytes along K
        cpa16(st +         d0, aSrcH + ko);
        cpa16(st +         d1, aSrcH + ko + 16);
        cpa16(st +  8192 + d0, aSrcL + ko);
        cpa16(st +  8192 + d1, aSrcL + ko + 16);
        cpa16(st + 16384 + d0, bSrcH + ko);
        cpa16(st + 16384 + d1, bSrcH + ko + 16);
        cpa16(st + 24576 + d0, bSrcL + ko);
        cpa16(st + 24576 + d1, bSrcL + ko + 16);
        CP_COMMIT();
    };

    issue(0, 0);
    if (NC > 1) issue(1, 1);

    float acc[4][4][4];
    #pragma unroll
    for (int a = 0; a < 4; a++)
        #pragma unroll
        for (int b = 0; b < 4; b++)
            #pragma unroll
            for (int r = 0; r < 4; r++) acc[a][b][r] = 0.0f;

    int stage = 0;
    for (int c = 0; c < NC; c++) {
        if (c < NC - 1) CP_WAIT(1); else CP_WAIT(0);
        __syncthreads();
        if (c + NSTAGE - 1 < NC)
            issue(c + NSTAGE - 1, (stage + NSTAGE - 1) % NSTAGE);

        uint32_t stA = sbase + stage * STG_SZ;
        uint32_t stB = stA + 16384;
        #pragma unroll
        for (int kk = 0; kk < 2; kk++) {
            uint32_t ah[4][4], al[4][4];
            #pragma unroll
            for (int mt = 0; mt < 4; mt++) {
                int r = wm * 64 + mt * 16 + (lane & 15);
                uint32_t c16 = kk * 2 + (lane >> 4);
                uint32_t off = r * 64 + ((c16 ^ ((r >> 1) & 3)) << 4);
                ldsm4(ah[mt], stA + off);
                ldsm4(al[mt], stA + 8192 + off);
            }
            uint32_t bh[2][4], bl[2][4];
            #pragma unroll
            for (int np = 0; np < 2; np++) {
                int r = wn * 32 + np * 16 + ((lane >> 4) << 3) + (lane & 7);
                uint32_t c16 = kk * 2 + ((lane >> 3) & 1);
                uint32_t off = r * 64 + ((c16 ^ ((r >> 1) & 3)) << 4);
                ldsm4(bh[np], stB + off);
                ldsm4(bl[np], stB + 8192 + off);
            }
            #pragma unroll
            for (int mt = 0; mt < 4; mt++)
                #pragma unroll
                for (int nt = 0; nt < 4; nt++) {
                    const uint32_t* ph = &bh[nt >> 1][(nt & 1) * 2];
                    const uint32_t* pl = &bl[nt >> 1][(nt & 1) * 2];
                    mma16816(acc[mt][nt], ah[mt], ph);
                    mma16816(acc[mt][nt], ah[mt], pl);
                    mma16816(acc[mt][nt], al[mt], ph);
                }
        }
        __syncthreads();
        stage = (stage + 1) % NSTAGE;
    }

    // epilogue
    int r0 = rowBase + wm * 64 + (lane >> 2);
    int c0 = colBase + wn * 32 + (lane & 3) * 2;
    #pragma unroll
    for (int nt = 0; nt < 4; nt++) {
        int col = c0 + nt * 8;
        float b0 = 0.0f, b1 = 0.0f;
        if (bias) { b0 = bias[col]; b1 = bias[col + 1]; }
        #pragma unroll
        for (int mt = 0; mt < 4; mt++) {
            int row = r0 + mt * 16;
            *(float2*)(C + (size_t)row * ldc + col) =
                make_float2(acc[mt][nt][0] * alpha + b0,
                            acc[mt][nt][1] * alpha + b1);
            *(float2*)(C + (size_t)(row + 8) * ldc + col) =
                make_float2(acc[mt][nt][2] * alpha + b0,
                            acc[mt][nt][3] * alpha + b1);
        }
    }
}

// ===========================================================================
// PV: O[g] = attn[g] @ V^T-tiles, scatter epilogue (R3-validated)
// ===========================================================================
#define PST 30720
#define PV_SMEM (2 * PST)

__global__ __launch_bounds__(256, 1) void pv_mma(
    const float* __restrict__ P,
    const __nv_bfloat16* __restrict__ vh, const __nv_bfloat16* __restrict__ vl,
    float* __restrict__ Out)
{
    extern __shared__ char smx[];
    uint32_t sbase = smem_u32(smx);

    int g = blockIdx.z;
    int rowBase = blockIdx.x * 128;
    const float* Pg = P + (size_t)g * ATTN_PER_G;
    const __nv_bfloat16* vhg = vh + (size_t)g * (DK * TSEQ);
    const __nv_bfloat16* vlg = vl + (size_t)g * (DK * TSEQ);

    int tid = threadIdx.x, lane = tid & 31, wid = tid >> 5;
    int wm = wid >> 1, wn = wid & 1;
    int lr = tid >> 1, lc = (tid & 1) * 16;
    int rowoff = lr * 80;

    const float* Abase = Pg + (size_t)(rowBase + lr) * TSEQ + lc;
    int bn = tid >> 2, bch = tid & 3;
    const __nv_bfloat16* BhBase = vhg + (size_t)bn * TSEQ + bch * 8;
    const __nv_bfloat16* BlBase = vlg + (size_t)bn * TSEQ + bch * 8;
    int boff = bn * 80 + bch * 16;

    float4 ra[4];
    uint4 rbh, rbl;
    #pragma unroll
    for (int i = 0; i < 4; i++) ra[i] = *(const float4*)(Abase + 4 * i);
    rbh = *(const uint4*)BhBase;
    rbl = *(const uint4*)BlBase;
    {
        char* s = smx;
        #pragma unroll
        for (int i = 0; i < 4; i++) {
            uint2 h, l;
            split_f4(ra[i], h, l);
            *(uint2*)(s +     0 + rowoff + (lc + 4 * i) * 2) = h;
            *(uint2*)(s + 10240 + rowoff + (lc + 4 * i) * 2) = l;
        }
        *(uint4*)(s + 20480 + boff) = rbh;
        *(uint4*)(s + 25600 + boff) = rbl;
    }
    __syncthreads();

    float acc[2][4][4];
    #pragma unroll
    for (int a = 0; a < 2; a++)
        #pragma unroll
        for (int b = 0; b < 4; b++)
            #pragma unroll
            for (int r = 0; r < 4; r++) acc[a][b][r] = 0.0f;

    const int NC = TSEQ / 32;
    for (int c = 0; c < NC; c++) {
        if (c + 1 < NC) {
            const float* ap = Abase + (c + 1) * 32;
            #pragma unroll
            for (int i = 0; i < 4; i++) ra[i] = *(const float4*)(ap + 4 * i);
            rbh = *(const uint4*)(BhBase + (c + 1) * 32);
            rbl = *(const uint4*)(BlBase + (c + 1) * 32);
        }
        uint32_t s0 = sbase + (c & 1) * PST;
        #pragma unroll
        for (int kk = 0; kk < 2; kk++) {
            uint32_t ah[2][4], al[2][4];
            #pragma unroll
            for (int mt = 0; mt < 2; mt++) {
                int row = wm * 32 + mt * 16 + (lane & 15);
                uint32_t off = row * 80 + kk * 32 + (lane >> 4) * 16;
                ldsm4(ah[mt], s0 + off);
                ldsm4(al[mt], s0 + 10240 + off);
            }
            uint32_t bh[2][4], bl[2][4];
            #pragma unroll
            for (int np = 0; np < 2; np++) {
                int nrow = wn * 32 + np * 16 + ((lane >> 4) << 3) + (lane & 7);
                uint32_t off = nrow * 80 + kk * 32 + ((lane >> 3) & 1) * 16;
                ldsm4(bh[np], s0 + 20480 + off);
                ldsm4(bl[np], s0 + 25600 + off);
            }
            #pragma unroll
            for (int mt = 0; mt < 2; mt++)
                #pragma unroll
                for (int nt = 0; nt < 4; nt++) {
                    const uint32_t* ph = &bh[nt >> 1][(nt & 1) * 2];
                    const uint32_t* pl = &bl[nt >> 1][(nt & 1) * 2];
                    mma16816(acc[mt][nt], ah[mt], ph);
                    mma16816(acc[mt][nt], ah[mt], pl);
                    mma16816(acc[mt][nt], al[mt], ph);
                }
        }
        if (c + 1 < NC) {
            char* s = smx + ((c + 1) & 1) * PST;
            #pragma unroll
            for (int i = 0; i < 4; i++) {
                uint2 h, l;
                split_f4(ra[i], h, l);
                *(uint2*)(s +     0 + rowoff + (lc + 4 * i) * 2) = h;
                *(uint2*)(s + 10240 + rowoff + (lc + 4 * i) * 2) = l;
            }
            *(uint4*)(s + 20480 + boff) = rbh;
            *(uint4*)(s + 25600 + boff) = rbl;
        }
        __syncthreads();
    }

    int b  = g >> 4;
    int gg = g & 15;
    float* ob = Out + (size_t)b * 2097152;
    int rr = rowBase + wm * 32 + (lane >> 2);
    int e0 = wn * 32 + (lane & 3) * 2;
    #pragma unroll
    for (int mt = 0; mt < 2; mt++) {
        #pragma unroll
        for (int half = 0; half < 2; half++) {
            int s   = rr + mt * 16 + half * 8;
            int thi = s >> 10;
            int d   = s & 1023;
            #pragma unroll
            for (int nt = 0; nt < 4; nt++) {
                int e  = e0 + nt * 8;
                int t0 = gg * 128 + 2 * e + thi;
                int t1 = gg * 128 + 2 * (e + 1) + thi;
                ob[(size_t)t0 * 1024 + d] = acc[mt][nt][half * 2 + 0];
                ob[(size_t)t1 * 1024 + d] = acc[mt][nt][half * 2 + 1];
            }
        }
    }
}

// ===========================================================================
// Row softmax in place
// ===========================================================================
__global__ __launch_bounds__(256) void softmax_kernel(float* __restrict__ attn)
{
    size_t row = blockIdx.x;
    float4* p = (float4*)attn + row * (TSEQ / 4);
    int tid = threadIdx.x;

    float4 a = p[tid];
    float4 b = p[tid + 256];

    float m = fmaxf(fmaxf(fmaxf(a.x, a.y), fmaxf(a.z, a.w)),
                    fmaxf(fmaxf(b.x, b.y), fmaxf(b.z, b.w)));
    #pragma unroll
    for (int o = 16; o > 0; o >>= 1) m = fmaxf(m, __shfl_xor_sync(0xffffffffu, m, o));

    __shared__ float ws[8];
    int w = tid >> 5, l = tid & 31;
    if (l == 0) ws[w] = m;
    __syncthreads();
    if (w == 0) {
        float s = (l < 8) ? ws[l] : -3.4e38f;
        #pragma unroll
        for (int o = 4; o > 0; o >>= 1) s = fmaxf(s, __shfl_xor_sync(0xffffffffu, s, o));
        if (l == 0) ws[0] = s;
    }
    __syncthreads();
    m = ws[0];
    __syncthreads();

    a.x = __expf(a.x - m); a.y = __expf(a.y - m);
    a.z = __expf(a.z - m); a.w = __expf(a.w - m);
    b.x = __expf(b.x - m); b.y = __expf(b.y - m);
    b.z = __expf(b.z - m); b.w = __expf(b.w - m);

    float ssum = a.x + a.y + a.z + a.w + b.x + b.y + b.z + b.w;
    #pragma unroll
    for (int o = 16; o > 0; o >>= 1) ssum += __shfl_xor_sync(0xffffffffu, ssum, o);
    if (l == 0) ws[w] = ssum;
    __syncthreads();
    if (w == 0) {
        float s = (l < 8) ? ws[l] : 0.0f;
        #pragma unroll
        for (int o = 4; o > 0; o >>= 1) s += __shfl_xor_sync(0xffffffffu, s, o);
        if (l == 0) ws[0] = s;
    }
    __syncthreads();
    float inv = 1.0f / ws[0];

    a.x *= inv; a.y *= inv; a.z *= inv; a.w *= inv;
    b.x *= inv; b.y *= inv; b.z *= inv; b.w *= inv;
    p[tid]       = a;
    p[tid + 256] = b;
}

// ===========================================================================
// kernel_launch
// ===========================================================================
extern "C" void kernel_launch(void* const* d_in, const int* in_sizes, int n_in,
                              void* d_out, int out_size)
{
    const float* x  = (const float*)d_in[0];
    const float* sc = (const float*)d_in[1];
    const float* wq = (const float*)d_in[2];
    const float* bq = (const float*)d_in[3];
    const float* wk = (const float*)d_in[4];
    const float* bk = (const float*)d_in[5];
    const float* wv = (const float*)d_in[6];
    const float* bv = (const float*)d_in[7];

    float* out  = (float*)d_out;
    float* attn = out + OUT_ELEMS;

    float *q, *k, *v;
    __nv_bfloat16 *xh, *xl, *qh, *ql, *kh, *kl, *wh, *wl, *vh, *vl;
    cudaGetSymbolAddress((void**)&q,  g_q);
    cudaGetSymbolAddress((void**)&k,  g_k);
    cudaGetSymbolAddress((void**)&v,  g_v);
    cudaGetSymbolAddress((void**)&xh, g_xh);
    cudaGetSymbolAddress((void**)&xl, g_xl);
    cudaGetSymbolAddress((void**)&qh, g_qh);
    cudaGetSymbolAddress((void**)&ql, g_ql);
    cudaGetSymbolAddress((void**)&kh, g_kh);
    cudaGetSymbolAddress((void**)&kl, g_kl);
    cudaGetSymbolAddress((void**)&wh, g_wh);
    cudaGetSymbolAddress((void**)&wl, g_wl);
    cudaGetSymbolAddress((void**)&vh, g_vh);
    cudaGetSymbolAddress((void**)&vl, g_vl);

    cudaFuncSetAttribute(gemm_bb, cudaFuncAttributeMaxDynamicSharedMemorySize, GB_SMEM);
    cudaFuncSetAttribute(pv_mma,  cudaFuncAttributeMaxDynamicSharedMemorySize, PV_SMEM);

    // 1) normalize x -> row-major hi/lo; split weights
    scalenorm_x<<<ROWS, 256>>>(x, sc, xh, xl);
    wsplit<<<3072, 256>>>(wq, wk, wv, wh, wl);

    // 2) projections: one batched launch (z = q/k/v)
    gemm_bb<<<dim3(8, 32, 3), 256, GB_SMEM>>>(
        0, xh, xl, wh, wl, bq, bk, bv, q, k, v,
        DMODEL, DMODEL, DMODEL, DMODEL, 1.0f);

    // 3) scale_norm q/k/v -> bf16 slabs (q,k), v in place
    scalenorm_qkv<<<dim3(ROWS, 3), 256>>>(q, k, v, sc, qh, ql, kh, kl);

    // 3b) V^T hi/lo split
    vt_convert<<<dim3(TSEQ / 64, 1, NGRP), 256>>>(v, vh, vl);

    // 4) S = Q K^T / 8 into attn region (z = group, lda=ldb=64)
    gemm_bb<<<dim3(16, 16, NGRP), 256, GB_SMEM>>>(
        1, qh, ql, kh, kl, nullptr, nullptr, nullptr, attn, nullptr, nullptr,
        DK, DK, TSEQ, DK, 0.125f);

    // 5) softmax in place
    softmax_kernel<<<NGRP * TSEQ, 256>>>(attn);

    // 6) O = attn @ V with scatter epilogue
    pv_mma<<<dim3(TSEQ / 128, 1, NGRP), 256, PV_SMEM>>>(attn, vh, vl, out);
}